// round 2
// baseline (speedup 1.0000x reference)
#include <cuda_runtime.h>
#include <cstdint>

// ---------------------------------------------------------------------------
// EEGConvNetMiniV3: GCN(128->16)+BN+LReLU -> SAGPool(0.5) -> GCN(16->32)+BN+
// LReLU -> SAGPool(0.5) -> global_add_pool -> MLP 32->8->4->2 (LReLU each).
// N=200000, E=6400000, single graph. edge_weigth unused (emask=1), b1/b2
// cancel inside BatchNorm.
// ---------------------------------------------------------------------------

#define NMAX  200000
#define EMAX  6400000
#define K1MAX 100000

// -------- static device scratch --------
__device__ float              g_hx1[NMAX * 16];   // x @ W1
__device__ float              g_h1 [NMAX * 16];   // agg1 -> bn/lrelu in place
__device__ float              g_p1 [NMAX];        // h1 @ Wr1
__device__ float              g_s1 [NMAX];        // score1
__device__ unsigned long long g_key1[NMAX];
__device__ int                g_inv1[NMAX];
__device__ float              g_hx2[K1MAX * 32];  // pooled feats @ W2
__device__ float              g_h2 [K1MAX * 32];  // agg2 -> bn/lrelu in place
__device__ float              g_p2 [K1MAX];
__device__ float              g_s2 [K1MAX];
__device__ unsigned long long g_key2[K1MAX];
__device__ int                g_src2[EMAX];
__device__ int                g_dst2[EMAX];
__device__ double             g_stats1[32];       // [sum(16) | sumsq(16)]
__device__ double             g_stats2[64];       // [sum(32) | sumsq(32)]
__device__ float              g_pooled[32];
__device__ int                g_n1;
__device__ int                g_e2;
__device__ unsigned int       g_hist[2][65536];

struct Sel {
    unsigned long long prefix;
    unsigned int       krem;
};
__device__ Sel g_sel[2];

// vector reduction: 16B atomic add (sm_90+)
__device__ __forceinline__ void red_add_v4(float* addr, float4 v) {
    asm volatile("red.global.add.v4.f32 [%0], {%1, %2, %3, %4};"
                 :: "l"(addr), "f"(v.x), "f"(v.y), "f"(v.z), "f"(v.w)
                 : "memory");
}

// ---------------------------------------------------------------------------
__global__ void k_init(int N, int K1, int K2) {
    long long tid    = blockIdx.x * (long long)blockDim.x + threadIdx.x;
    long long stride = (long long)gridDim.x * blockDim.x;
    for (long long t = tid; t < (long long)N * 16; t += stride) g_h1[t] = 0.f;
    for (long long t = tid; t < (long long)K1 * 32; t += stride) g_h2[t] = 0.f;
    for (long long t = tid; t < N; t += stride) g_inv1[t] = -1;
    for (long long t = tid; t < 131072; t += stride) ((unsigned*)g_hist)[t] = 0u;
    if (tid < 32)  g_stats1[tid] = 0.0;
    if (tid < 64)  g_stats2[tid] = 0.0;
    if (tid < 32)  g_pooled[tid] = 0.f;
    if (tid == 0) {
        g_n1 = 0; g_e2 = 0;
        g_sel[0].prefix = 0ull; g_sel[0].krem = (unsigned)K1;
        g_sel[1].prefix = 0ull; g_sel[1].krem = (unsigned)K2;
    }
}

// x (N x 128) @ W1 (128 x 16) -> g_hx1
__global__ __launch_bounds__(256) void k_gemm1(const float* __restrict__ x,
                                               const float* __restrict__ W1, int N) {
    __shared__ float sW[128 * 16];
    __shared__ float sX[16 * 128];
    int tid  = threadIdx.x;
    int row0 = blockIdx.x * 16;
    for (int j = tid; j < 2048; j += 256) sW[j] = W1[j];
    for (int j = tid; j < 2048; j += 256) {
        int r = j >> 7, c = j & 127;
        int row = row0 + r;
        sX[j] = (row < N) ? x[(long long)row * 128 + c] : 0.f;
    }
    __syncthreads();
    int r = tid >> 4, f = tid & 15;
    float acc = 0.f;
#pragma unroll 16
    for (int k = 0; k < 128; k++) acc += sX[r * 128 + k] * sW[k * 16 + f];
    int row = row0 + r;
    if (row < N) g_hx1[(long long)row * 16 + f] = acc;
}

// one thread per edge: 4 x float4 gather + 4 x red.v4 scatter
__global__ __launch_bounds__(256) void k_edge_agg16(const int* __restrict__ src,
                                                    const int* __restrict__ dst, int E) {
    int e = blockIdx.x * blockDim.x + threadIdx.x;
    if (e >= E) return;
    int s = src[e], d = dst[e];
    const float4* hs = (const float4*)&g_hx1[(long long)s * 16];
    float*        hd = &g_h1[(long long)d * 16];
#pragma unroll
    for (int j = 0; j < 4; j++) red_add_v4(hd + 4 * j, hs[j]);
}

// row-major vectorized BN stats. GROUPS = F/4; group fixed per thread.
template <int F>
__global__ __launch_bounds__(256) void k_bnstats(int n) {
    const float4* h4    = (const float4*)((F == 16) ? g_h1 : g_h2);
    double*       stats = (F == 16) ? g_stats1 : g_stats2;
    const int G = F / 4;
    int tid = threadIdx.x;
    int g   = tid & (G - 1);             // blockDim %G==0 and stride %G==0
    long long total  = (long long)n * G;
    long long stride = (long long)gridDim.x * blockDim.x;
    float4 s = {0, 0, 0, 0}, q = {0, 0, 0, 0};
    for (long long t = blockIdx.x * (long long)blockDim.x + tid; t < total; t += stride) {
        float4 v = h4[t];
        s.x += v.x; s.y += v.y; s.z += v.z; s.w += v.w;
        q.x += v.x * v.x; q.y += v.y * v.y; q.z += v.z * v.z; q.w += v.w * v.w;
    }
    __shared__ float ss[256][4], sq[256][4];
    ss[tid][0] = s.x; ss[tid][1] = s.y; ss[tid][2] = s.z; ss[tid][3] = s.w;
    sq[tid][0] = q.x; sq[tid][1] = q.y; sq[tid][2] = q.z; sq[tid][3] = q.w;
    __syncthreads();
    if (tid < G) {
        double as[4] = {0, 0, 0, 0}, aq[4] = {0, 0, 0, 0};
        for (int j = tid; j < 256; j += G) {
#pragma unroll
            for (int c = 0; c < 4; c++) { as[c] += ss[j][c]; aq[c] += sq[j][c]; }
        }
#pragma unroll
        for (int c = 0; c < 4; c++) {
            atomicAdd(&stats[tid * 4 + c],     as[c]);
            atomicAdd(&stats[F + tid * 4 + c], aq[c]);
        }
    }
}

// BN (training stats) + LeakyReLU in place, plus score precomputation:
//   p[i] = h[i] @ Wr   (to be edge-aggregated),  s[i] = h[i] @ Wroot + br
template <int F>
__global__ __launch_bounds__(256) void k_bnapply(int n,
                                                 const float* __restrict__ gam,
                                                 const float* __restrict__ beta,
                                                 const float* __restrict__ Wr,
                                                 const float* __restrict__ br,
                                                 const float* __restrict__ Wroot) {
    float*  h     = (F == 16) ? g_h1 : g_h2;
    float*  p     = (F == 16) ? g_p1 : g_p2;
    float*  s     = (F == 16) ? g_s1 : g_s2;
    double* stats = (F == 16) ? g_stats1 : g_stats2;

    __shared__ float smu[F], ssc[F], sbe[F], sWr[F], sWt[F];
    if (threadIdx.x < F) {
        int    f   = threadIdx.x;
        double mu  = stats[f] / (double)n;
        double var = stats[F + f] / (double)n - mu * mu;
        smu[f] = (float)mu;
        ssc[f] = gam[f] * rsqrtf((float)var + 1e-5f);
        sbe[f] = beta[f];
        sWr[f] = Wr[f];
        sWt[f] = Wroot[f];
    }
    __syncthreads();
    long long i = blockIdx.x * (long long)blockDim.x + threadIdx.x;
    if (i >= n) return;
    float dotp = 0.f, dotr = 0.f;
#pragma unroll
    for (int f = 0; f < F; f++) {
        float v = h[i * F + f];
        v = (v - smu[f]) * ssc[f] + sbe[f];
        v = v > 0.f ? v : 0.01f * v;
        h[i * F + f] = v;
        dotp += v * sWr[f];
        dotr += v * sWt[f];
    }
    p[i] = dotp;
    s[i] = dotr + br[0];
}

__global__ __launch_bounds__(256) void k_edge_scalar1(const int* __restrict__ src,
                                                      const int* __restrict__ dst, int E) {
    int e = blockIdx.x * blockDim.x + threadIdx.x;
    if (e >= E) return;
    atomicAdd(&g_s1[dst[e]], g_p1[src[e]]);
}

__global__ __launch_bounds__(256) void k_makekeys(int which, int n) {
    const float*        s   = which ? g_s2 : g_s1;
    unsigned long long* key = which ? g_key2 : g_key1;
    int i = blockIdx.x * blockDim.x + threadIdx.x;
    if (i >= n) return;
    unsigned u = __float_as_uint(s[i]);
    u = (u & 0x80000000u) ? ~u : (u | 0x80000000u);
    key[i] = ((unsigned long long)u << 32) | (unsigned long long)(0xFFFFFFFFu - (unsigned)i);
}

// MSB radix-select with 16-bit digits: 4 passes of (hist, scan)
__global__ __launch_bounds__(256) void k_hist16(int which, int n, int pass) {
    const unsigned long long* key = which ? g_key2 : g_key1;
    unsigned*                 hist = g_hist[which];
    unsigned long long prefix = g_sel[which].prefix;
    int                shift  = 48 - 16 * pass;
    unsigned long long mask   = pass ? (~0ull << (64 - 16 * pass)) : 0ull;
    for (long long i = blockIdx.x * (long long)blockDim.x + threadIdx.x; i < n;
         i += (long long)gridDim.x * blockDim.x) {
        unsigned long long k = key[i];
        if (((k ^ prefix) & mask) == 0ull)
            atomicAdd(&hist[(unsigned)(k >> shift) & 0xFFFFu], 1u);
    }
}

__global__ __launch_bounds__(1024) void k_scan16(int which, int pass) {
    __shared__ unsigned part[1024];
    Sel*      S    = &g_sel[which];
    unsigned* hist = g_hist[which];
    int t = threadIdx.x;
    unsigned krem = S->krem;

    unsigned own = 0;
#pragma unroll 4
    for (int j = 0; j < 64; j++) own += hist[t * 64 + j];
    part[t] = own;
    __syncthreads();
    // inclusive suffix sum (Hillis-Steele)
    for (int off = 1; off < 1024; off <<= 1) {
        unsigned add = (t + off < 1024) ? part[t + off] : 0u;
        __syncthreads();
        part[t] += add;
        __syncthreads();
    }
    unsigned suf_incl = part[t];
    unsigned suf_excl = suf_incl - own;
    if (suf_incl >= krem && suf_excl < krem) {
        unsigned acc = suf_excl;
        int chosen = 0; unsigned newkrem = krem;
        for (int j = 63; j >= 0; --j) {
            unsigned c = hist[t * 64 + j];
            if (acc + c >= krem) { chosen = t * 64 + j; newkrem = krem - acc; break; }
            acc += c;
        }
        S->prefix |= ((unsigned long long)chosen) << (48 - 16 * pass);
        S->krem = newkrem;
    }
    // zero own bins for next pass
#pragma unroll 4
    for (int j = 0; j < 64; j++) hist[t * 64 + j] = 0u;
}

// keep key >= threshold; compute hk = h1*tanh(s1), then hx2 = hk @ W2 fused
__global__ __launch_bounds__(256) void k_compact_nodes(const float* __restrict__ W2, int N) {
    __shared__ float sW[16 * 32];
    for (int j = threadIdx.x; j < 512; j += 256) sW[j] = W2[j];
    __syncthreads();
    int i = blockIdx.x * blockDim.x + threadIdx.x;
    if (i >= N) return;
    if (g_key1[i] >= g_sel[0].prefix) {
        int   pos = atomicAdd(&g_n1, 1);
        g_inv1[i] = pos;
        float tn = tanhf(g_s1[i]);
        float hk[16];
#pragma unroll
        for (int f = 0; f < 16; f++) hk[f] = g_h1[(long long)i * 16 + f] * tn;
#pragma unroll
        for (int o = 0; o < 32; o++) {
            float acc = 0.f;
#pragma unroll
            for (int f = 0; f < 16; f++) acc += hk[f] * sW[f * 32 + o];
            g_hx2[(long long)pos * 32 + o] = acc;
        }
    }
}

__global__ __launch_bounds__(256) void k_compact_edges(const int* __restrict__ src,
                                                       const int* __restrict__ dst, int E) {
    int e = blockIdx.x * blockDim.x + threadIdx.x;
    if (e >= E) return;
    int ns = g_inv1[src[e]];
    int nd = g_inv1[dst[e]];
    if ((ns | nd) >= 0) {
        int pos = atomicAdd(&g_e2, 1);
        g_src2[pos] = ns;
        g_dst2[pos] = nd;
    }
}

__global__ __launch_bounds__(256) void k_edge_agg32() {
    int E2 = g_e2;
    for (int e = blockIdx.x * blockDim.x + threadIdx.x; e < E2;
         e += gridDim.x * blockDim.x) {
        int s = g_src2[e], d = g_dst2[e];
        const float4* hs = (const float4*)&g_hx2[(long long)s * 32];
        float*        hd = &g_h2[(long long)d * 32];
#pragma unroll
        for (int j = 0; j < 8; j++) red_add_v4(hd + 4 * j, hs[j]);
    }
}

__global__ __launch_bounds__(256) void k_edge_scalar2() {
    int E2 = g_e2;
    for (int e = blockIdx.x * blockDim.x + threadIdx.x; e < E2;
         e += gridDim.x * blockDim.x)
        atomicAdd(&g_s2[g_dst2[e]], g_p2[g_src2[e]]);
}

// sum over kept stage-2 nodes of h2 * tanh(s2) -> g_pooled[32]
__global__ __launch_bounds__(256) void k_pool(int K1) {
    __shared__ float part[32];
    if (threadIdx.x < 32) part[threadIdx.x] = 0.f;
    __syncthreads();
    unsigned long long T = g_sel[1].prefix;
    int   g = threadIdx.x & 7;           // fixed group: blockDim %8==0, stride %8==0
    float a0 = 0.f, a1 = 0.f, a2 = 0.f, a3 = 0.f;
    long long total  = (long long)K1 * 8;
    long long stride = (long long)gridDim.x * blockDim.x;
    for (long long t = blockIdx.x * (long long)blockDim.x + threadIdx.x; t < total;
         t += stride) {
        long long i = t >> 3;
        if (g_key2[i] >= T) {
            float  tn = tanhf(g_s2[i]);
            float4 v  = ((const float4*)g_h2)[t];
            a0 += v.x * tn; a1 += v.y * tn; a2 += v.z * tn; a3 += v.w * tn;
        }
    }
    atomicAdd(&part[g * 4 + 0], a0);
    atomicAdd(&part[g * 4 + 1], a1);
    atomicAdd(&part[g * 4 + 2], a2);
    atomicAdd(&part[g * 4 + 3], a3);
    __syncthreads();
    if (threadIdx.x < 32) atomicAdd(&g_pooled[threadIdx.x], part[threadIdx.x]);
}

__global__ void k_mlp(const float* __restrict__ fw1, const float* __restrict__ fb1,
                      const float* __restrict__ fw2, const float* __restrict__ fb2,
                      const float* __restrict__ fw3, const float* __restrict__ fb3,
                      float* __restrict__ out) {
    if (threadIdx.x == 0 && blockIdx.x == 0) {
        float a[8], b[4];
#pragma unroll
        for (int o = 0; o < 8; o++) {
            float v = fb1[o];
            for (int j = 0; j < 32; j++) v += g_pooled[j] * fw1[j * 8 + o];
            a[o] = v > 0.f ? v : 0.01f * v;
        }
#pragma unroll
        for (int o = 0; o < 4; o++) {
            float v = fb2[o];
            for (int j = 0; j < 8; j++) v += a[j] * fw2[j * 4 + o];
            b[o] = v > 0.f ? v : 0.01f * v;
        }
#pragma unroll
        for (int o = 0; o < 2; o++) {
            float v = fb3[o];
            for (int j = 0; j < 4; j++) v += b[j] * fw3[j * 2 + o];
            out[o] = v > 0.f ? v : 0.01f * v;
        }
    }
}

// ---------------------------------------------------------------------------
extern "C" void kernel_launch(void* const* d_in, const int* in_sizes, int n_in,
                              void* d_out, int out_size) {
    const float* x   = (const float*)d_in[0];
    const int*   ei  = (const int*)d_in[1];
    int          E   = in_sizes[2];      // edge_weigth count
    int          N   = in_sizes[3];      // batch count
    const int*   src = ei;
    const int*   dst = ei + E;
    int K1 = (N + 1) / 2;
    int K2 = (K1 + 1) / 2;

    const float* W1     = (const float*)d_in[4];
    const float* g1     = (const float*)d_in[6];
    const float* be1    = (const float*)d_in[7];
    const float* Wr1    = (const float*)d_in[8];
    const float* br1    = (const float*)d_in[9];
    const float* Wroot1 = (const float*)d_in[10];
    const float* W2     = (const float*)d_in[11];
    const float* g2     = (const float*)d_in[13];
    const float* be2    = (const float*)d_in[14];
    const float* Wr2    = (const float*)d_in[15];
    const float* br2    = (const float*)d_in[16];
    const float* Wroot2 = (const float*)d_in[17];
    const float* fw1    = (const float*)d_in[18];
    const float* fb1    = (const float*)d_in[19];
    const float* fw2    = (const float*)d_in[20];
    const float* fb2    = (const float*)d_in[21];
    const float* fw3    = (const float*)d_in[22];
    const float* fb3    = (const float*)d_in[23];
    float*       out    = (float*)d_out;

    // ---- init scratch ----
    k_init<<<2048, 256>>>(N, K1, K2);

    // ---- stage 1: GCN + BN + LReLU ----
    k_gemm1<<<(N + 15) / 16, 256>>>(x, W1, N);
    k_edge_agg16<<<(E + 255) / 256, 256>>>(src, dst, E);
    k_bnstats<16><<<512, 256>>>(N);
    k_bnapply<16><<<(N + 255) / 256, 256>>>(N, g1, be1, Wr1, br1, Wroot1);

    // ---- stage 1 score + top-k select ----
    k_edge_scalar1<<<(E + 255) / 256, 256>>>(src, dst, E);
    k_makekeys<<<(N + 255) / 256, 256>>>(0, N);
    for (int p = 0; p < 4; p++) {
        k_hist16<<<128, 256>>>(0, N, p);
        k_scan16<<<1, 1024>>>(0, p);
    }
    k_compact_nodes<<<(N + 255) / 256, 256>>>(W2, N);
    k_compact_edges<<<(E + 255) / 256, 256>>>(src, dst, E);

    // ---- stage 2: GCN + BN + LReLU ----
    k_edge_agg32<<<4096, 256>>>();
    k_bnstats<32><<<512, 256>>>(K1);
    k_bnapply<32><<<(K1 + 255) / 256, 256>>>(K1, g2, be2, Wr2, br2, Wroot2);

    // ---- stage 2 score + top-k select ----
    k_edge_scalar2<<<2048, 256>>>();
    k_makekeys<<<(K1 + 255) / 256, 256>>>(1, K1);
    for (int p = 0; p < 4; p++) {
        k_hist16<<<64, 256>>>(1, K1, p);
        k_scan16<<<1, 1024>>>(1, p);
    }

    // ---- global add pool + MLP ----
    k_pool<<<256, 256>>>(K1);
    k_mlp<<<1, 32>>>(fw1, fb1, fw2, fb2, fw3, fb3, out);
}

// round 3
// speedup vs baseline: 1.1181x; 1.1181x over previous
#include <cuda_runtime.h>
#include <cstdint>

// ---------------------------------------------------------------------------
// EEGConvNetMiniV3: GCN(128->16)+BN+LReLU -> SAGPool(0.5) -> GCN(16->32)+BN+
// LReLU -> SAGPool(0.5) -> global_add_pool -> MLP 32->8->4->2 (LReLU each).
// N=200000, E=6400000, single graph. edge_weigth unused (emask=1), b1/b2
// cancel inside BatchNorm.
// ---------------------------------------------------------------------------

#define NMAX  200000
#define EMAX  6400000
#define K1MAX 100000

// -------- static device scratch --------
__device__ float              g_hx1[NMAX * 16];   // x @ W1
__device__ float              g_h1 [NMAX * 16];   // agg1 -> bn/lrelu in place
__device__ float              g_p1 [NMAX];        // h1 @ Wr1
__device__ float              g_s1 [NMAX];        // score1
__device__ unsigned long long g_key1[NMAX];
__device__ int                g_inv1[NMAX];
__device__ float              g_hx2[K1MAX * 32];  // pooled feats @ W2
__device__ float              g_h2 [K1MAX * 32];  // agg2 -> bn/lrelu in place
__device__ float              g_p2 [K1MAX];
__device__ float              g_s2 [K1MAX];
__device__ unsigned long long g_key2[K1MAX];
__device__ int                g_src2[EMAX];
__device__ int                g_dst2[EMAX];
__device__ double             g_stats1[32];       // [sum(16) | sumsq(16)]
__device__ double             g_stats2[64];       // [sum(32) | sumsq(32)]
__device__ float              g_pooled[32];
__device__ int                g_n1;
__device__ int                g_e2;
__device__ unsigned int       g_hist[2][65536];

struct Sel {
    unsigned long long prefix;
    unsigned int       krem;
};
__device__ Sel g_sel[2];

// 8-byte vector reduction (sm_90+)
__device__ __forceinline__ void red_add_v2(float* addr, float2 v) {
    asm volatile("red.global.add.v2.f32 [%0], {%1, %2};"
                 :: "l"(addr), "f"(v.x), "f"(v.y)
                 : "memory");
}

// ---------------------------------------------------------------------------
__global__ void k_init(int N, int K1, int K2) {
    long long tid    = blockIdx.x * (long long)blockDim.x + threadIdx.x;
    long long stride = (long long)gridDim.x * blockDim.x;
    for (long long t = tid; t < (long long)N * 16; t += stride) g_h1[t] = 0.f;
    for (long long t = tid; t < (long long)K1 * 32; t += stride) g_h2[t] = 0.f;
    for (long long t = tid; t < N; t += stride) g_inv1[t] = -1;
    for (long long t = tid; t < 131072; t += stride) ((unsigned*)g_hist)[t] = 0u;
    if (tid < 32)  g_stats1[tid] = 0.0;
    if (tid < 64)  g_stats2[tid] = 0.0;
    if (tid < 32)  g_pooled[tid] = 0.f;
    if (tid == 0) {
        g_n1 = 0; g_e2 = 0;
        g_sel[0].prefix = 0ull; g_sel[0].krem = (unsigned)K1;
        g_sel[1].prefix = 0ull; g_sel[1].krem = (unsigned)K2;
    }
}

// x (N x 128) @ W1 (128 x 16) -> g_hx1
__global__ __launch_bounds__(256) void k_gemm1(const float* __restrict__ x,
                                               const float* __restrict__ W1, int N) {
    __shared__ float sW[128 * 16];
    __shared__ float sX[16 * 128];
    int tid  = threadIdx.x;
    int row0 = blockIdx.x * 16;
    for (int j = tid; j < 2048; j += 256) sW[j] = W1[j];
    for (int j = tid; j < 2048; j += 256) {
        int r = j >> 7, c = j & 127;
        int row = row0 + r;
        sX[j] = (row < N) ? x[(long long)row * 128 + c] : 0.f;
    }
    __syncthreads();
    int r = tid >> 4, f = tid & 15;
    float acc = 0.f;
#pragma unroll 16
    for (int k = 0; k < 128; k++) acc += sX[r * 128 + k] * sW[k * 16 + f];
    int row = row0 + r;
    if (row < N) g_hx1[(long long)row * 16 + f] = acc;
}

// 8 threads per edge: coalesced float2 gather + red.v2 scatter
__global__ __launch_bounds__(256) void k_edge_agg16(const int* __restrict__ src,
                                                    const int* __restrict__ dst,
                                                    long long E8) {
    long long t = blockIdx.x * (long long)blockDim.x + threadIdx.x;
    if (t >= E8) return;
    int       f = (int)(t & 7);
    long long e = t >> 3;
    int s = src[e], d = dst[e];
    float2 v = ((const float2*)g_hx1)[(long long)s * 8 + f];
    red_add_v2((float*)&((float2*)g_h1)[(long long)d * 8 + f], v);
}

// BN stats (R1 proven shape): feature fixed per thread, strided rows
template <int F>
__global__ __launch_bounds__(256) void k_bnstats(int n) {
    const float* h     = (F == 16) ? g_h1 : g_h2;
    double*      stats = (F == 16) ? g_stats1 : g_stats2;
    int tid = threadIdx.x;
    int f   = tid % F;
    const int rpb = 256 / F;
    float s = 0.f, sq = 0.f;
    for (long long row = blockIdx.x * (long long)rpb + tid / F; row < n;
         row += (long long)gridDim.x * rpb) {
        float v = h[row * F + f];
        s += v; sq += v * v;
    }
    __shared__ float sh[256], shq[256];
    sh[tid] = s; shq[tid] = sq;
    __syncthreads();
    if (tid < F) {
        float a = 0.f, b = 0.f;
        for (int j = tid; j < 256; j += F) { a += sh[j]; b += shq[j]; }
        atomicAdd(&stats[f],     (double)a);
        atomicAdd(&stats[F + f], (double)b);
    }
}

// BN (training stats) + LeakyReLU in place, plus score precomputation:
//   p[i] = h[i] @ Wr   (to be edge-aggregated),  s[i] = h[i] @ Wroot + br
template <int F>
__global__ __launch_bounds__(256) void k_bnapply(int n,
                                                 const float* __restrict__ gam,
                                                 const float* __restrict__ beta,
                                                 const float* __restrict__ Wr,
                                                 const float* __restrict__ br,
                                                 const float* __restrict__ Wroot) {
    float*  h     = (F == 16) ? g_h1 : g_h2;
    float*  p     = (F == 16) ? g_p1 : g_p2;
    float*  s     = (F == 16) ? g_s1 : g_s2;
    double* stats = (F == 16) ? g_stats1 : g_stats2;

    __shared__ float smu[F], ssc[F], sbe[F], sWr[F], sWt[F];
    if (threadIdx.x < F) {
        int    f   = threadIdx.x;
        double mu  = stats[f] / (double)n;
        double var = stats[F + f] / (double)n - mu * mu;
        smu[f] = (float)mu;
        ssc[f] = gam[f] * rsqrtf((float)var + 1e-5f);
        sbe[f] = beta[f];
        sWr[f] = Wr[f];
        sWt[f] = Wroot[f];
    }
    __syncthreads();
    long long i = blockIdx.x * (long long)blockDim.x + threadIdx.x;
    if (i >= n) return;
    float dotp = 0.f, dotr = 0.f;
#pragma unroll
    for (int f = 0; f < F; f++) {
        float v = h[i * F + f];
        v = (v - smu[f]) * ssc[f] + sbe[f];
        v = v > 0.f ? v : 0.01f * v;
        h[i * F + f] = v;
        dotp += v * sWr[f];
        dotr += v * sWt[f];
    }
    p[i] = dotp;
    s[i] = dotr + br[0];
}

__global__ __launch_bounds__(256) void k_edge_scalar1(const int* __restrict__ src,
                                                      const int* __restrict__ dst, int E) {
    int e = blockIdx.x * blockDim.x + threadIdx.x;
    if (e >= E) return;
    atomicAdd(&g_s1[dst[e]], g_p1[src[e]]);
}

// pass 0 of radix select fused with key construction
__global__ __launch_bounds__(256) void k_keyhist0(int which, int n) {
    const float*        s    = which ? g_s2 : g_s1;
    unsigned long long* key  = which ? g_key2 : g_key1;
    unsigned*           hist = g_hist[which];
    for (long long i = blockIdx.x * (long long)blockDim.x + threadIdx.x; i < n;
         i += (long long)gridDim.x * blockDim.x) {
        unsigned u = __float_as_uint(s[i]);
        u = (u & 0x80000000u) ? ~u : (u | 0x80000000u);
        unsigned long long k =
            ((unsigned long long)u << 32) | (unsigned long long)(0xFFFFFFFFu - (unsigned)i);
        key[i] = k;
        atomicAdd(&hist[(unsigned)(k >> 48)], 1u);
    }
}

// passes 1..3: histogram of next 16 bits among prefix-matching keys
__global__ __launch_bounds__(256) void k_hist16(int which, int n, int pass) {
    const unsigned long long* key  = which ? g_key2 : g_key1;
    unsigned*                 hist = g_hist[which];
    unsigned long long prefix = g_sel[which].prefix;
    int                shift  = 48 - 16 * pass;
    unsigned long long mask   = ~0ull << (64 - 16 * pass);
    for (long long i = blockIdx.x * (long long)blockDim.x + threadIdx.x; i < n;
         i += (long long)gridDim.x * blockDim.x) {
        unsigned long long k = key[i];
        if (((k ^ prefix) & mask) == 0ull)
            atomicAdd(&hist[(unsigned)(k >> shift) & 0xFFFFu], 1u);
    }
}

__global__ __launch_bounds__(1024) void k_scan16(int which, int pass) {
    __shared__ unsigned part[1024];
    Sel*      S    = &g_sel[which];
    unsigned* hist = g_hist[which];
    int t = threadIdx.x;
    unsigned krem = S->krem;

    unsigned own = 0;
#pragma unroll 4
    for (int j = 0; j < 64; j++) own += hist[t * 64 + j];
    part[t] = own;
    __syncthreads();
    // inclusive suffix sum (Hillis-Steele)
    for (int off = 1; off < 1024; off <<= 1) {
        unsigned add = (t + off < 1024) ? part[t + off] : 0u;
        __syncthreads();
        part[t] += add;
        __syncthreads();
    }
    unsigned suf_incl = part[t];
    unsigned suf_excl = suf_incl - own;
    if (suf_incl >= krem && suf_excl < krem) {
        unsigned acc = suf_excl;
        int chosen = 0; unsigned newkrem = krem;
        for (int j = 63; j >= 0; --j) {
            unsigned c = hist[t * 64 + j];
            if (acc + c >= krem) { chosen = t * 64 + j; newkrem = krem - acc; break; }
            acc += c;
        }
        S->prefix |= ((unsigned long long)chosen) << (48 - 16 * pass);
        S->krem = newkrem;
    }
    // zero own bins for next pass
#pragma unroll 4
    for (int j = 0; j < 64; j++) hist[t * 64 + j] = 0u;
}

// keep key >= threshold; compute hk = h1*tanh(s1), then hx2 = hk @ W2 fused
__global__ __launch_bounds__(256) void k_compact_nodes(const float* __restrict__ W2, int N) {
    __shared__ float sW[16 * 32];
    for (int j = threadIdx.x; j < 512; j += 256) sW[j] = W2[j];
    __syncthreads();
    int i = blockIdx.x * blockDim.x + threadIdx.x;
    if (i >= N) return;
    if (g_key1[i] >= g_sel[0].prefix) {
        int   pos = atomicAdd(&g_n1, 1);
        g_inv1[i] = pos;
        float tn = tanhf(g_s1[i]);
        float hk[16];
#pragma unroll
        for (int f = 0; f < 16; f++) hk[f] = g_h1[(long long)i * 16 + f] * tn;
#pragma unroll
        for (int o = 0; o < 32; o++) {
            float acc = 0.f;
#pragma unroll
            for (int f = 0; f < 16; f++) acc += hk[f] * sW[f * 32 + o];
            g_hx2[(long long)pos * 32 + o] = acc;
        }
    }
}

__global__ __launch_bounds__(256) void k_compact_edges(const int* __restrict__ src,
                                                       const int* __restrict__ dst, int E) {
    int e = blockIdx.x * blockDim.x + threadIdx.x;
    if (e >= E) return;
    int ns = g_inv1[src[e]];
    int nd = g_inv1[dst[e]];
    if ((ns | nd) >= 0) {
        int pos = atomicAdd(&g_e2, 1);
        g_src2[pos] = ns;
        g_dst2[pos] = nd;
    }
}

// 16 threads per edge: coalesced float2 gather + red.v2 scatter
__global__ __launch_bounds__(256) void k_edge_agg32() {
    long long total  = (long long)g_e2 * 16;
    long long stride = (long long)gridDim.x * blockDim.x;
    for (long long t = blockIdx.x * (long long)blockDim.x + threadIdx.x; t < total;
         t += stride) {
        int       f = (int)(t & 15);
        long long e = t >> 4;
        int s = g_src2[e], d = g_dst2[e];
        float2 v = ((const float2*)g_hx2)[(long long)s * 16 + f];
        red_add_v2((float*)&((float2*)g_h2)[(long long)d * 16 + f], v);
    }
}

__global__ __launch_bounds__(256) void k_edge_scalar2() {
    int E2 = g_e2;
    for (int e = blockIdx.x * blockDim.x + threadIdx.x; e < E2;
         e += gridDim.x * blockDim.x)
        atomicAdd(&g_s2[g_dst2[e]], g_p2[g_src2[e]]);
}

// sum over kept stage-2 nodes of h2 * tanh(s2) -> g_pooled[32]
__global__ __launch_bounds__(256) void k_pool(int K1) {
    __shared__ float part[32];
    if (threadIdx.x < 32) part[threadIdx.x] = 0.f;
    __syncthreads();
    unsigned long long T = g_sel[1].prefix;
    int   g = threadIdx.x & 7;           // fixed group: blockDim %8==0, stride %8==0
    float a0 = 0.f, a1 = 0.f, a2 = 0.f, a3 = 0.f;
    long long total  = (long long)K1 * 8;
    long long stride = (long long)gridDim.x * blockDim.x;
    for (long long t = blockIdx.x * (long long)blockDim.x + threadIdx.x; t < total;
         t += stride) {
        long long i = t >> 3;
        if (g_key2[i] >= T) {
            float  tn = tanhf(g_s2[i]);
            float4 v  = ((const float4*)g_h2)[t];
            a0 += v.x * tn; a1 += v.y * tn; a2 += v.z * tn; a3 += v.w * tn;
        }
    }
    atomicAdd(&part[g * 4 + 0], a0);
    atomicAdd(&part[g * 4 + 1], a1);
    atomicAdd(&part[g * 4 + 2], a2);
    atomicAdd(&part[g * 4 + 3], a3);
    __syncthreads();
    if (threadIdx.x < 32) atomicAdd(&g_pooled[threadIdx.x], part[threadIdx.x]);
}

__global__ void k_mlp(const float* __restrict__ fw1, const float* __restrict__ fb1,
                      const float* __restrict__ fw2, const float* __restrict__ fb2,
                      const float* __restrict__ fw3, const float* __restrict__ fb3,
                      float* __restrict__ out) {
    if (threadIdx.x == 0 && blockIdx.x == 0) {
        float a[8], b[4];
#pragma unroll
        for (int o = 0; o < 8; o++) {
            float v = fb1[o];
            for (int j = 0; j < 32; j++) v += g_pooled[j] * fw1[j * 8 + o];
            a[o] = v > 0.f ? v : 0.01f * v;
        }
#pragma unroll
        for (int o = 0; o < 4; o++) {
            float v = fb2[o];
            for (int j = 0; j < 8; j++) v += a[j] * fw2[j * 4 + o];
            b[o] = v > 0.f ? v : 0.01f * v;
        }
#pragma unroll
        for (int o = 0; o < 2; o++) {
            float v = fb3[o];
            for (int j = 0; j < 4; j++) v += b[j] * fw3[j * 2 + o];
            out[o] = v > 0.f ? v : 0.01f * v;
        }
    }
}

// ---------------------------------------------------------------------------
extern "C" void kernel_launch(void* const* d_in, const int* in_sizes, int n_in,
                              void* d_out, int out_size) {
    const float* x   = (const float*)d_in[0];
    const int*   ei  = (const int*)d_in[1];
    int          E   = in_sizes[2];      // edge_weigth count
    int          N   = in_sizes[3];      // batch count
    const int*   src = ei;
    const int*   dst = ei + E;
    int K1 = (N + 1) / 2;
    int K2 = (K1 + 1) / 2;

    const float* W1     = (const float*)d_in[4];
    const float* g1     = (const float*)d_in[6];
    const float* be1    = (const float*)d_in[7];
    const float* Wr1    = (const float*)d_in[8];
    const float* br1    = (const float*)d_in[9];
    const float* Wroot1 = (const float*)d_in[10];
    const float* W2     = (const float*)d_in[11];
    const float* g2     = (const float*)d_in[13];
    const float* be2    = (const float*)d_in[14];
    const float* Wr2    = (const float*)d_in[15];
    const float* br2    = (const float*)d_in[16];
    const float* Wroot2 = (const float*)d_in[17];
    const float* fw1    = (const float*)d_in[18];
    const float* fb1    = (const float*)d_in[19];
    const float* fw2    = (const float*)d_in[20];
    const float* fb2    = (const float*)d_in[21];
    const float* fw3    = (const float*)d_in[22];
    const float* fb3    = (const float*)d_in[23];
    float*       out    = (float*)d_out;

    // ---- init scratch ----
    k_init<<<2048, 256>>>(N, K1, K2);

    // ---- stage 1: GCN + BN + LReLU ----
    k_gemm1<<<(N + 15) / 16, 256>>>(x, W1, N);
    {
        long long E8 = (long long)E * 8;
        k_edge_agg16<<<(int)((E8 + 255) / 256), 256>>>(src, dst, E8);
    }
    k_bnstats<16><<<512, 256>>>(N);
    k_bnapply<16><<<(N + 255) / 256, 256>>>(N, g1, be1, Wr1, br1, Wroot1);

    // ---- stage 1 score + top-k select ----
    k_edge_scalar1<<<(E + 255) / 256, 256>>>(src, dst, E);
    k_keyhist0<<<256, 256>>>(0, N);
    k_scan16<<<1, 1024>>>(0, 0);
    for (int p = 1; p < 4; p++) {
        k_hist16<<<128, 256>>>(0, N, p);
        k_scan16<<<1, 1024>>>(0, p);
    }
    k_compact_nodes<<<(N + 255) / 256, 256>>>(W2, N);
    k_compact_edges<<<(E + 255) / 256, 256>>>(src, dst, E);

    // ---- stage 2: GCN + BN + LReLU ----
    k_edge_agg32<<<8192, 256>>>();
    k_bnstats<32><<<512, 256>>>(K1);
    k_bnapply<32><<<(K1 + 255) / 256, 256>>>(K1, g2, be2, Wr2, br2, Wroot2);

    // ---- stage 2 score + top-k select ----
    k_edge_scalar2<<<2048, 256>>>();
    k_keyhist0<<<128, 256>>>(1, K1);
    k_scan16<<<1, 1024>>>(1, 0);
    for (int p = 1; p < 4; p++) {
        k_hist16<<<64, 256>>>(1, K1, p);
        k_scan16<<<1, 1024>>>(1, p);
    }

    // ---- global add pool + MLP ----
    k_pool<<<256, 256>>>(K1);
    k_mlp<<<1, 32>>>(fw1, fb1, fw2, fb2, fw3, fb3, out);
}